// round 6
// baseline (speedup 1.0000x reference)
#include <cuda_runtime.h>
#include <cstdint>

#define T_STEPS 4096
#define RES     2048
#define DIMS    64
#define NCTA    128
#define ROWS_PER_CTA 16   // RES / NCTA
#define THREADS_ESN  512
#define NGROUPS 1024      // RES/2 groups of {h0,h1,tag,pad}

// ---------------- scratch (static device globals; no runtime allocs) ----------------
__device__ float g_U[(size_t)T_STEPS * DIMS];        // [t][d]
__device__ float g_G[(size_t)RES * T_STEPS];         // [r][t]  (W_in @ u_t, precomputed)
__device__ float g_H[(size_t)T_STEPS * RES];         // [t][r]  (reservoir states, for k_out)
__device__ __align__(16) unsigned int g_buf[2][NGROUPS * 4];  // [parity][group*4] = {h0,h1,tag,pad}

// packed f32x2 FMA (Blackwell)
__device__ __forceinline__ unsigned long long ffma2(unsigned long long a,
                                                    unsigned long long b,
                                                    unsigned long long c) {
    unsigned long long d;
    asm("fma.rn.f32x2 %0, %1, %2, %3;" : "=l"(d) : "l"(a), "l"(b), "l"(c));
    return d;
}

// fast tanh: 1 - 2/(exp(2x)+1); 2 MUFU ops, rel err ~2e-7/step (budget 1e-3)
__device__ __forceinline__ float ftanh(float x) {
    float e = __expf(2.0f * x);
    return 1.0f - __fdividef(2.0f, e + 1.0f);
}

// ---------------- kernel 1: U[t][d] = C@x_t; also zero the exchange buffers ---------
__global__ __launch_bounds__(256) void k_u(const float* __restrict__ X,
                                           const float* __restrict__ C) {
    __shared__ float Cs[64][65];
    __shared__ float xs[4][64];
    int tid = threadIdx.x;
    int b = blockIdx.x;
    for (int i = tid; i < 64 * 64; i += 256) Cs[i >> 6][i & 63] = C[i];
    int tl = tid >> 6, d = tid & 63;
    int t = b * 4 + tl;
    xs[tl][d] = X[t * 64 + d];
    __syncthreads();
    float acc = 0.f;
#pragma unroll
    for (int i = 0; i < 64; i++) acc = fmaf(Cs[d][i], xs[tl][i], acc);
    g_U[t * 64 + d] = acc;
    // zero both parity buffers (2 * 1024 * 4 = 8192 ints) so stale tags never match
    int gi = b * 256 + tid;
    if (gi < 2 * NGROUPS * 4) ((unsigned int*)g_buf)[gi] = 0u;
}

// ---------------- kernel 2: G[r][t] = sum_d W_in[r][d] * U[t][d] --------------------
__global__ __launch_bounds__(512) void k_g(const float* __restrict__ Win) {
    __shared__ float Us[32][65];
    int tid = threadIdx.x, w = tid >> 5, l = tid & 31;
    int t0 = blockIdx.x * 32;
    for (int i = tid; i < 32 * 64; i += 512) Us[i >> 6][i & 63] = g_U[t0 * 64 + i];
    __syncthreads();
    for (int k = 0; k < 128; k++) {
        int r = w * 128 + k;
        const float* wrow = Win + r * 64;
        float acc = 0.f;
#pragma unroll
        for (int d = 0; d < 64; d++) acc = fmaf(__ldg(wrow + d), Us[l][d], acc);
        g_G[(size_t)r * T_STEPS + t0 + l] = acc;
    }
}

// ---------------- kernel 3: persistent reservoir recurrence -------------------------
// 128 CTAs x 512 threads, CTA c owns rows [16c,16c+16) of W_res in registers.
// Warp w consumes ONLY h-columns [128w,128w+128): lane l polls exactly the 16B
// chunks h[128w+4l..+4) it feeds into its FMAs -> warp-local consume (no CTA-wide
// scatter barrier). Warps 0-7 reduce row PAIRS (lanes 0-15: row 2w, 16-31: row
// 2w+1) and publish dense 16B tagged groups; warps 8-15 race ahead to the next
// step's poll. parts[] is parity-double-buffered to make the race-ahead safe.
__global__ __launch_bounds__(THREADS_ESN, 1) void k_esn(const float* __restrict__ Wres) {
    __shared__ __align__(16) float hsm[RES];
    __shared__ float parts[2][16][17];       // [step parity][row][colblock warp]

    int tid = threadIdx.x, w = tid >> 5, l = tid & 31;
    int cta = blockIdx.x;
    int row = l >> 1, half = l & 1;
    int grow = cta * ROWS_PER_CTA + row;     // global row this lane accumulates
    int prow = 2 * w + (l >= 16);            // row-in-CTA this lane reduces (warps 0-7)

    // Load this lane's 64 W_res weights as 32 packed f32x2 operands (same as R2).
    unsigned long long wreg[32];
    {
        const ulonglong2* wp = reinterpret_cast<const ulonglong2*>(
            Wres + (size_t)grow * RES + w * 128 + half * 4);
#pragma unroll
        for (int j = 0; j < 16; j++) {
            ulonglong2 v = wp[j * 2];        // 16B at float offset j*8
            wreg[2 * j]     = v.x;
            wreg[2 * j + 1] = v.y;
        }
    }

    for (int t = 0; t < T_STEPS; t++) {
        unsigned int tag = (unsigned int)t;
        const unsigned int* bufin = g_buf[t & 1];
        unsigned int* bufout = g_buf[(t + 1) & 1];

        // prefetch G for the row this lane will reduce (warps 0-7; off critical path)
        float gval = 0.f;
        if (w < 8) gval = __ldg(&g_G[(size_t)(cta * ROWS_PER_CTA + prow) * T_STEPS + t]);

        // ---- poll this lane's OWN 16B chunks: groups 64w+2l, 64w+2l+1 -------------
        unsigned int a0 = 0, a1 = 0, b0 = 0, b1 = 0;
        if (t > 0) {
            const unsigned int* p0 = bufin + (size_t)(64 * w + 2 * l) * 4;
            const unsigned int* p1 = p0 + 4;
            unsigned int a2, a3, b2, b3;
            bool d0 = false, d1 = false;
            do {
                if (!d0) {
                    asm volatile("ld.global.cg.v4.u32 {%0,%1,%2,%3},[%4];"
                                 : "=r"(a0), "=r"(a1), "=r"(a2), "=r"(a3) : "l"(p0));
                    d0 = (a2 == tag);
                }
                if (!d1) {
                    asm volatile("ld.global.cg.v4.u32 {%0,%1,%2,%3},[%4];"
                                 : "=r"(b0), "=r"(b1), "=r"(b2), "=r"(b3) : "l"(p1));
                    d1 = (b2 == tag);
                }
            } while (!(d0 && d1));
        }
        // warp-local: h[128w+4l..+4) -> smem (t=0 writes zeros, covers all of hsm)
        *reinterpret_cast<float4*>(hsm + w * 128 + 4 * l) =
            make_float4(__uint_as_float(a0), __uint_as_float(a1),
                        __uint_as_float(b0), __uint_as_float(b1));
        __syncwarp();

        // ---- partial dot over this lane's 64 columns (packed f32x2, as R2) --------
        const ulonglong2* hp = reinterpret_cast<const ulonglong2*>(
            hsm + w * 128 + half * 4);
        unsigned long long acc0 = 0ull, acc1 = 0ull;
#pragma unroll
        for (int j = 0; j < 16; j++) {
            ulonglong2 hv = hp[j * 2];       // LDS.128, broadcast across rows: conflict-free
            acc0 = ffma2(wreg[2 * j],     hv.x, acc0);
            acc1 = ffma2(wreg[2 * j + 1], hv.y, acc1);
        }
        float s = __uint_as_float((unsigned)acc0) +
                  __uint_as_float((unsigned)(acc0 >> 32)) +
                  __uint_as_float((unsigned)acc1) +
                  __uint_as_float((unsigned)(acc1 >> 32));
        s += __shfl_xor_sync(0xffffffffu, s, 1);        // combine the two halves
        if (half == 0) parts[t & 1][row][w] = s;
        __syncthreads();                                 // the ONLY CTA barrier/step

        // ---- warps 0-7: reduce row pair (2w, 2w+1), tanh, publish 16B group -------
        if (w < 8) {
            float v = parts[t & 1][prow][l & 15];
            v += __shfl_xor_sync(0xffffffffu, v, 8);     // butterflies stay in 16-lane halves
            v += __shfl_xor_sync(0xffffffffu, v, 4);
            v += __shfl_xor_sync(0xffffffffu, v, 2);
            v += __shfl_xor_sync(0xffffffffu, v, 1);
            float hv = ftanh(v + gval);                  // lanes 0-15: h_{2w}; 16-31: h_{2w+1}
            float h1 = __shfl_sync(0xffffffffu, hv, 16);
            if (l == 0) {
                unsigned int* p = bufout + (size_t)(cta * 8 + w) * 4;
                asm volatile("st.global.cg.v4.u32 [%0], {%1,%2,%3,%4};"
                             :: "l"(p), "r"(__float_as_uint(hv)), "r"(__float_as_uint(h1)),
                                "r"((unsigned int)(t + 1)), "r"(0u) : "memory");
            }
            if (l == 0 || l == 16)                       // stash for k_out (off critical path)
                g_H[(size_t)t * RES + cta * ROWS_PER_CTA + prow] = hv;
        }
        // warps 8-15 (and 0-7 after publish) fall through to the next step's poll.
    }
}

// ---------------- kernel 4: y[t] = dW[0:64].U[t] + dW[64:].H[t] + b ------------------
__global__ __launch_bounds__(256) void k_out(const float* __restrict__ dW,
                                             const float* __restrict__ db,
                                             float* __restrict__ y) {
    int t = blockIdx.x, tid = threadIdx.x;
    float acc = 0.f;
    if (tid < 64) acc = dW[tid] * g_U[t * 64 + tid];
    for (int r = tid; r < RES; r += 256)
        acc = fmaf(dW[64 + r], g_H[(size_t)t * RES + r], acc);
#pragma unroll
    for (int o = 16; o; o >>= 1) acc += __shfl_xor_sync(0xffffffffu, acc, o);
    __shared__ float red[8];
    if ((tid & 31) == 0) red[tid >> 5] = acc;
    __syncthreads();
    if (tid < 8) {
        float v = red[tid];
        v += __shfl_xor_sync(0xffu, v, 4);
        v += __shfl_xor_sync(0xffu, v, 2);
        v += __shfl_xor_sync(0xffu, v, 1);
        if (tid == 0) y[t] = v + db[0];
    }
}

// ---------------- launcher ----------------------------------------------------------
extern "C" void kernel_launch(void* const* d_in, const int* in_sizes, int n_in,
                              void* d_out, int out_size) {
    const float* X    = (const float*)d_in[0];   // (4096, 64, 1)
    const float* C    = (const float*)d_in[1];   // (64, 64)
    const float* Win  = (const float*)d_in[2];   // (2048, 64)
    const float* Wres = (const float*)d_in[3];   // (2048, 2048)
    const float* dW   = (const float*)d_in[4];   // (1, 2112)
    const float* db   = (const float*)d_in[5];   // (1,)
    float* y = (float*)d_out;                    // (4096, 1, 1)

    k_u  <<<T_STEPS / 4, 256>>>(X, C);           // also zeroes g_buf tags
    k_g  <<<T_STEPS / 32, 512>>>(Win);
    k_esn<<<NCTA, THREADS_ESN>>>(Wres);
    k_out<<<T_STEPS, 256>>>(dW, db, y);
}